// round 1
// baseline (speedup 1.0000x reference)
#include <cuda_runtime.h>
#include <cstdint>

#define BATCH 8
#define NN 4096
#define FF 128
#define UU 64
#define LOG2E 1.4426950408889634f

// Scratch (device globals: no allocation allowed)
__device__ float g_X[BATCH * NN * UU];   // X = H@W, fp32
__device__ float g_s[BATCH * NN];        // (X@a1) * log2e
__device__ float g_t[BATCH * NN];        // (X@a2) * log2e

__device__ __forceinline__ float ex2f(float x) {
    float r;
    asm("ex2.approx.f32 %0, %1;" : "=f"(r) : "f"(x));
    return r;
}
__device__ __forceinline__ float tf32r(float x) {
    float y;
    asm("cvt.rna.tf32.f32 %0, %1;" : "=f"(y) : "f"(x));
    return y;
}

// ---------------------------------------------------------------------------
// Kernel 1: X[b,n,:] = H[b,n,:] @ W   (fp32, tiled). 512 CTAs x 256 thr.
// CTA computes 64 rows x 64 cols, K=128 in two 64-chunks.
// ---------------------------------------------------------------------------
__global__ void __launch_bounds__(256) xgemm_kernel(const float* __restrict__ H,
                                                    const float* __restrict__ W) {
    __shared__ float Hst[64][68];  // [k][row], padded
    __shared__ float Ws[64][64];   // [k][u]
    const int row0 = blockIdx.x * 64;      // global row in [0, B*N)
    const int t = threadIdx.x;
    const int ty = t >> 4, tx = t & 15;    // 16x16 thread grid, 4x4 micro-tile

    float acc[4][4];
#pragma unroll
    for (int i = 0; i < 4; ++i)
#pragma unroll
        for (int j = 0; j < 4; ++j) acc[i][j] = 0.f;

    for (int kk = 0; kk < 2; ++kk) {
#pragma unroll
        for (int q = 0; q < 4; ++q) {
            int idx = t + q * 256;          // float4 index 0..1023
            int r = idx >> 4, c4 = idx & 15;
            float4 v = *(const float4*)(H + (size_t)(row0 + r) * FF + kk * 64 + c4 * 4);
            Hst[c4 * 4 + 0][r] = v.x;
            Hst[c4 * 4 + 1][r] = v.y;
            Hst[c4 * 4 + 2][r] = v.z;
            Hst[c4 * 4 + 3][r] = v.w;
            float4 wv = *(const float4*)(W + (size_t)(kk * 64 + r) * UU + c4 * 4);
            *(float4*)&Ws[r][c4 * 4] = wv;
        }
        __syncthreads();
#pragma unroll
        for (int k = 0; k < 64; ++k) {
            float4 a = *(float4*)&Hst[k][ty * 4];
            float4 bv = *(float4*)&Ws[k][tx * 4];
            float ar[4] = {a.x, a.y, a.z, a.w};
            float br[4] = {bv.x, bv.y, bv.z, bv.w};
#pragma unroll
            for (int i = 0; i < 4; ++i)
#pragma unroll
                for (int j = 0; j < 4; ++j) acc[i][j] += ar[i] * br[j];
        }
        __syncthreads();
    }
#pragma unroll
    for (int i = 0; i < 4; ++i) {
        float4 v = make_float4(acc[i][0], acc[i][1], acc[i][2], acc[i][3]);
        *(float4*)(g_X + (size_t)(row0 + ty * 4 + i) * UU + tx * 4) = v;
    }
}

// ---------------------------------------------------------------------------
// Kernel 2: s = (X@a1)*log2e, t = (X@a2)*log2e. One warp per row.
// ---------------------------------------------------------------------------
__global__ void __launch_bounds__(256) st_kernel(const float* __restrict__ a1,
                                                 const float* __restrict__ a2) {
    int gw = (blockIdx.x * blockDim.x + threadIdx.x) >> 5;  // row id
    int lane = threadIdx.x & 31;
    float x0 = g_X[(size_t)gw * UU + lane];
    float x1 = g_X[(size_t)gw * UU + 32 + lane];
    float sv = x0 * a1[lane] + x1 * a1[lane + 32];
    float tv = x0 * a2[lane] + x1 * a2[lane + 32];
#pragma unroll
    for (int o = 16; o; o >>= 1) {
        sv += __shfl_xor_sync(0xffffffffu, sv, o);
        tv += __shfl_xor_sync(0xffffffffu, tv, o);
    }
    if (lane == 0) {
        g_s[gw] = sv * LOG2E;
        g_t[gw] = tv * LOG2E;
    }
}

// ---------------------------------------------------------------------------
// Kernel 3: fused mask + softmax(unnormalized) + P@X via mma.sync tf32.
// Grid (32, 8): blockIdx.x = i-tile (128 rows), blockIdx.y = batch.
// 8 warps; warp w owns rows [i0+16w, i0+16w+16), all 64 U columns.
// Per j-tile of 64: coalesced A loads -> P (tf32) in smem -> 64 mma.sync.
// Z accumulated per-lane in registers across all tiles, reduced once.
// Smem: Xs[u=64][stride 68] + Ps[8 warps][16][stride 68]  = 52224 B dynamic.
// Stride 68 => frag-read bank index = (4g+tig+c)%32 = (lane+c)%32: conflict-free.
// ---------------------------------------------------------------------------
#define SMEM_MAIN ((64 * 68 + 8 * 16 * 68) * 4)

__global__ void __launch_bounds__(256, 2) gat_kernel(const float* __restrict__ A,
                                                     float* __restrict__ out) {
    extern __shared__ float sm[];
    float* Xs = sm;                 // [64][68] : Xs[u*68 + j]
    float* Ps = sm + 64 * 68;       // [8][16][68]

    const int b = blockIdx.y;
    const int i0 = blockIdx.x * 128;
    const int tid = threadIdx.x;
    const int w = tid >> 5, lane = tid & 31;
    const int g = lane >> 2, tig = lane & 3;
    const int wrow0 = i0 + w * 16;
    float* Psw = Ps + w * 16 * 68;

    float sreg[16];
#pragma unroll
    for (int r = 0; r < 16; ++r) sreg[r] = g_s[b * NN + wrow0 + r];

    float4 acc[8];
#pragma unroll
    for (int nb = 0; nb < 8; ++nb) acc[nb] = make_float4(0.f, 0.f, 0.f, 0.f);
    float zpart[16];
#pragma unroll
    for (int r = 0; r < 16; ++r) zpart[r] = 0.f;

    const size_t Abase = ((size_t)b * NN + wrow0) * NN;
    const float* Xb = g_X + (size_t)b * NN * UU;
    const float* tb = g_t + b * NN;

    for (int jt = 0; jt < NN / 64; ++jt) {
        const int j0 = jt * 64;
        __syncthreads();  // all warps done reading previous Xs
        // Load X tile transposed: Xs[u][j] = tf32(X[b][j0+j][u])
#pragma unroll
        for (int q = 0; q < 4; ++q) {
            int idx = tid + q * 256;       // float4 idx 0..1023
            int j = idx >> 4, c4 = idx & 15;
            float4 v = *(const float4*)(Xb + (size_t)(j0 + j) * UU + c4 * 4);
            Xs[(c4 * 4 + 0) * 68 + j] = tf32r(v.x);
            Xs[(c4 * 4 + 1) * 68 + j] = tf32r(v.y);
            Xs[(c4 * 4 + 2) * 68 + j] = tf32r(v.z);
            Xs[(c4 * 4 + 3) * 68 + j] = tf32r(v.w);
        }
        __syncthreads();

        float tv0 = tb[j0 + lane];
        float tv1 = tb[j0 + 32 + lane];

        // P stage (warp-private): p = A * exp2(leaky(s'+t'))
#pragma unroll
        for (int r = 0; r < 16; ++r) {
            const float* Ar = A + Abase + (size_t)r * NN + j0;
            float m0 = Ar[lane];
            float m1 = Ar[lane + 32];
            float l0 = sreg[r] + tv0;
            float l1 = sreg[r] + tv1;
            l0 = fmaxf(l0, 0.2f * l0);   // leaky relu (slope 0.2)
            l1 = fmaxf(l1, 0.2f * l1);
            float e0 = tf32r(ex2f(l0) * m0);
            float e1 = tf32r(ex2f(l1) * m1);
            zpart[r] += e0 + e1;
            Psw[r * 68 + lane] = e0;
            Psw[r * 68 + lane + 32] = e1;
        }
        __syncwarp();

        // MMA stage: D[16x64] += P[16x64] @ X[64x64]^T (tf32, 8 k-chunks x 8 n-blocks)
#pragma unroll
        for (int kc = 0; kc < 8; ++kc) {
            const int jc = kc * 8 + tig;
            uint32_t a0 = __float_as_uint(Psw[g * 68 + jc]);
            uint32_t a1 = __float_as_uint(Psw[(g + 8) * 68 + jc]);
            uint32_t a2v = __float_as_uint(Psw[g * 68 + jc + 4]);
            uint32_t a3 = __float_as_uint(Psw[(g + 8) * 68 + jc + 4]);
#pragma unroll
            for (int nb = 0; nb < 8; ++nb) {
                uint32_t b0 = __float_as_uint(Xs[(nb * 8 + g) * 68 + jc]);
                uint32_t b1 = __float_as_uint(Xs[(nb * 8 + g) * 68 + jc + 4]);
                asm volatile(
                    "mma.sync.aligned.m16n8k8.row.col.f32.tf32.tf32.f32 "
                    "{%0,%1,%2,%3}, {%4,%5,%6,%7}, {%8,%9}, {%0,%1,%2,%3};\n"
                    : "+f"(acc[nb].x), "+f"(acc[nb].y), "+f"(acc[nb].z), "+f"(acc[nb].w)
                    : "r"(a0), "r"(a1), "r"(a2v), "r"(a3), "r"(b0), "r"(b1));
            }
        }
    }

    // Epilogue: reduce Z per row, divide, relu, store.
    __syncwarp();                 // all lanes done reading Psw (WAR before reuse)
    float* Zs = Psw;              // reuse warp-private smem for 16 Z values
#pragma unroll
    for (int r = 0; r < 16; ++r) {
        float v = zpart[r];
#pragma unroll
        for (int o = 16; o; o >>= 1) v += __shfl_xor_sync(0xffffffffu, v, o);
        if (lane == r) Zs[r] = v;
    }
    __syncwarp();
    float inv0 = 1.0f / Zs[g];
    float inv1 = 1.0f / Zs[g + 8];

    float* outb = out + ((size_t)b * NN + wrow0) * UU;
#pragma unroll
    for (int nb = 0; nb < 8; ++nb) {
        int col = nb * 8 + tig * 2;
        float2 v0 = make_float2(fmaxf(acc[nb].x * inv0, 0.f), fmaxf(acc[nb].y * inv0, 0.f));
        float2 v1 = make_float2(fmaxf(acc[nb].z * inv1, 0.f), fmaxf(acc[nb].w * inv1, 0.f));
        *(float2*)(outb + (size_t)g * UU + col) = v0;
        *(float2*)(outb + (size_t)(g + 8) * UU + col) = v1;
    }
}

// ---------------------------------------------------------------------------
extern "C" void kernel_launch(void* const* d_in, const int* in_sizes, int n_in,
                              void* d_out, int out_size) {
    const float* H = (const float*)d_in[0];       // [8,4096,128]
    const float* Amask = (const float*)d_in[1];   // [8,4096,4096]
    const float* W = (const float*)d_in[2];       // [128,64]
    const float* a1 = (const float*)d_in[3];      // [64,1]
    const float* a2 = (const float*)d_in[4];      // [64,1]
    float* out = (float*)d_out;                   // [8,4096,64]

    cudaFuncSetAttribute(gat_kernel, cudaFuncAttributeMaxDynamicSharedMemorySize, SMEM_MAIN);

    xgemm_kernel<<<(BATCH * NN) / 64, 256>>>(H, W);
    st_kernel<<<(BATCH * NN) / 8, 256>>>(a1, a2);
    gat_kernel<<<dim3(NN / 128, BATCH), 256, SMEM_MAIN>>>(Amask, out);
}

// round 4
// speedup vs baseline: 1.6423x; 1.6423x over previous
#include <cuda_runtime.h>
#include <cstdint>

#define BATCH 8
#define NN 4096
#define FF 128
#define UU 64
#define LOG2E 1.4426950408889634f

// ---------------- device scratch (no allocations allowed) -------------------
__device__ float  g_X[BATCH * NN * UU];   // X = H@W (fp32)
__device__ float2 g_es2[BATCH * NN];      // (2^s~, 2^{0.2 s~})
__device__ float2 g_et2[BATCH * NN];      // (2^t~, 2^{0.2 t~})

// ---------------- helpers ---------------------------------------------------
__device__ __forceinline__ float ex2f(float x) {
    float r; asm("ex2.approx.f32 %0, %1;" : "=f"(r) : "f"(x)); return r;
}
__device__ __forceinline__ float tf32r(float x) {
    float y; asm("cvt.rna.tf32.f32 %0, %1;" : "=f"(y) : "f"(x)); return y;
}

// ---------------------------------------------------------------------------
// Kernel 1: X = H @ W  (fp32, tiled). 512 CTAs x 256 thr.
// ---------------------------------------------------------------------------
__global__ void __launch_bounds__(256) xgemm_kernel(const float* __restrict__ H,
                                                    const float* __restrict__ W) {
    __shared__ float Hst[64][68];
    __shared__ float Ws[64][64];
    const int row0 = blockIdx.x * 64;
    const int t = threadIdx.x;
    const int ty = t >> 4, tx = t & 15;

    float acc[4][4];
#pragma unroll
    for (int i = 0; i < 4; ++i)
#pragma unroll
        for (int j = 0; j < 4; ++j) acc[i][j] = 0.f;

    for (int kk = 0; kk < 2; ++kk) {
#pragma unroll
        for (int q = 0; q < 4; ++q) {
            int idx = t + q * 256;
            int r = idx >> 4, c4 = idx & 15;
            float4 v = *(const float4*)(H + (size_t)(row0 + r) * FF + kk * 64 + c4 * 4);
            Hst[c4 * 4 + 0][r] = v.x;
            Hst[c4 * 4 + 1][r] = v.y;
            Hst[c4 * 4 + 2][r] = v.z;
            Hst[c4 * 4 + 3][r] = v.w;
            float4 wv = *(const float4*)(W + (size_t)(kk * 64 + r) * UU + c4 * 4);
            *(float4*)&Ws[r][c4 * 4] = wv;
        }
        __syncthreads();
#pragma unroll
        for (int k = 0; k < 64; ++k) {
            float4 a = *(float4*)&Hst[k][ty * 4];
            float4 bv = *(float4*)&Ws[k][tx * 4];
            float ar[4] = {a.x, a.y, a.z, a.w};
            float br[4] = {bv.x, bv.y, bv.z, bv.w};
#pragma unroll
            for (int i = 0; i < 4; ++i)
#pragma unroll
                for (int j = 0; j < 4; ++j) acc[i][j] += ar[i] * br[j];
        }
        __syncthreads();
    }
#pragma unroll
    for (int i = 0; i < 4; ++i) {
        float4 v = make_float4(acc[i][0], acc[i][1], acc[i][2], acc[i][3]);
        *(float4*)(g_X + (size_t)(row0 + ty * 4 + i) * UU + tx * 4) = v;
    }
}

// ---------------------------------------------------------------------------
// Kernel 2: per-row exp factors. s~ = (X@a1)*log2e, t~ = (X@a2)*log2e
// ---------------------------------------------------------------------------
__global__ void __launch_bounds__(256) st_kernel(const float* __restrict__ a1,
                                                 const float* __restrict__ a2) {
    int gw = (blockIdx.x * blockDim.x + threadIdx.x) >> 5;
    int lane = threadIdx.x & 31;
    float x0 = g_X[(size_t)gw * UU + lane];
    float x1 = g_X[(size_t)gw * UU + 32 + lane];
    float sv = x0 * a1[lane] + x1 * a1[lane + 32];
    float tv = x0 * a2[lane] + x1 * a2[lane + 32];
#pragma unroll
    for (int o = 16; o; o >>= 1) {
        sv += __shfl_xor_sync(0xffffffffu, sv, o);
        tv += __shfl_xor_sync(0xffffffffu, tv, o);
    }
    if (lane == 0) {
        sv *= LOG2E; tv *= LOG2E;
        g_es2[gw] = make_float2(ex2f(sv), ex2f(0.2f * sv));
        g_et2[gw] = make_float2(ex2f(tv), ex2f(0.2f * tv));
    }
}

// ---------------------------------------------------------------------------
// Kernel 3: fused mask + unnormalized softmax + P@X via mma.sync tf32.
// Grid (32, 8). CTA = 128 i-rows x 64 U-cols; loop over 64 j-tiles of 64.
// Warp w owns P-rows [16w, 16w+16). Half-warp lane layout for the P stage:
//   h = lane>>4, c = lane&15; lane handles rows (it + 8h), cols 4c..4c+3.
// P smem row stride 68 words => mma fragment reads are bank-conflict-free.
// ---------------------------------------------------------------------------
#define SMEM_MAIN ((64 * 68 + 8 * 16 * 68 + 128) * 4)

__global__ void __launch_bounds__(256, 2) gat_kernel(const float* __restrict__ A,
                                                     float* __restrict__ out) {
    extern __shared__ float sm[];
    float* Xs = sm;                      // [64][68] : Xs[u*68 + j]
    float* Ps = sm + 64 * 68;            // [8 warps][16][68]
    float* Zs = sm + 64 * 68 + 8 * 16 * 68;  // [128]

    const int b = blockIdx.y;
    const int i0 = blockIdx.x * 128;
    const int tid = threadIdx.x;
    const int w = tid >> 5, lane = tid & 31;
    const int g = lane >> 2, tig = lane & 3;
    const int h = lane >> 4, c = lane & 15;
    const int wrow0 = i0 + w * 16;
    float* Psw = Ps + w * 16 * 68;

    // per-row exp factors for the 8 rows this lane touches (rows it + 8h)
    float2 esv[8];
    {
        const float2* esp = g_es2 + (size_t)b * NN + wrow0 + 8 * h;
#pragma unroll
        for (int it = 0; it < 8; ++it) esv[it] = esp[it];
    }

    float4 acc[8];
#pragma unroll
    for (int nb = 0; nb < 8; ++nb) acc[nb] = make_float4(0.f, 0.f, 0.f, 0.f);
    float zp[8];
#pragma unroll
    for (int it = 0; it < 8; ++it) zp[it] = 0.f;

    const float* Abase = A + ((size_t)b * NN + wrow0 + 8 * h) * NN + 4 * c;
    const float2* etb = g_et2 + (size_t)b * NN + 4 * c;
    const float* Xb = g_X + (size_t)b * NN * UU;

    for (int jt = 0; jt < NN / 64; ++jt) {
        const int j0 = jt * 64;
        __syncthreads();  // everyone done with previous Xs / P
        // --- X tile transposed into smem: Xs[u][j] = tf32(X[j0+j][u]) ---
#pragma unroll
        for (int q = 0; q < 4; ++q) {
            int idx = tid + q * 256;          // float4 idx 0..1023
            int j = idx >> 4, c4 = idx & 15;
            float4 v = *(const float4*)(Xb + (size_t)(j0 + j) * UU + c4 * 4);
            Xs[(c4 * 4 + 0) * 68 + j] = tf32r(v.x);
            Xs[(c4 * 4 + 1) * 68 + j] = tf32r(v.y);
            Xs[(c4 * 4 + 2) * 68 + j] = tf32r(v.z);
            Xs[(c4 * 4 + 3) * 68 + j] = tf32r(v.w);
        }
        __syncthreads();

        // --- column factors for this lane's 4 columns ---
        float4 et01 = *(const float4*)(etb + j0);       // (et[4c], et[4c+1])
        float4 et23 = *(const float4*)(etb + j0 + 2);   // (et[4c+2], et[4c+3])

        // --- P stage: p = A * max(Es*Et, Es5*Et5) ---
        const float* Ap = Abase + (size_t)j0;
#pragma unroll
        for (int it = 0; it < 8; ++it) {
            float4 m = __ldcs((const float4*)(Ap + (size_t)it * NN));
            float esx = esv[it].x, esy = esv[it].y;
            float e0 = tf32r(m.x * fmaxf(esx * et01.x, esy * et01.y));
            float e1 = tf32r(m.y * fmaxf(esx * et01.z, esy * et01.w));
            float e2 = tf32r(m.z * fmaxf(esx * et23.x, esy * et23.y));
            float e3 = tf32r(m.w * fmaxf(esx * et23.z, esy * et23.w));
            zp[it] += (e0 + e1) + (e2 + e3);
            *(float4*)&Psw[(it + 8 * h) * 68 + 4 * c] = make_float4(e0, e1, e2, e3);
        }
        __syncwarp();

        // --- MMA: D[16x64] += P[16x64] @ X[64x64]^T  (8 kc x 8 nb) ---
#pragma unroll
        for (int kc = 0; kc < 8; ++kc) {
            const int jc = kc * 8 + tig;
            uint32_t a0 = __float_as_uint(Psw[g * 68 + jc]);
            uint32_t a1 = __float_as_uint(Psw[(g + 8) * 68 + jc]);
            uint32_t a2v = __float_as_uint(Psw[g * 68 + jc + 4]);
            uint32_t a3 = __float_as_uint(Psw[(g + 8) * 68 + jc + 4]);
#pragma unroll
            for (int nb = 0; nb < 8; ++nb) {
                uint32_t b0 = __float_as_uint(Xs[(nb * 8 + g) * 68 + jc]);
                uint32_t b1 = __float_as_uint(Xs[(nb * 8 + g) * 68 + jc + 4]);
                asm volatile(
                    "mma.sync.aligned.m16n8k8.row.col.f32.tf32.tf32.f32 "
                    "{%0,%1,%2,%3}, {%4,%5,%6,%7}, {%8,%9}, {%0,%1,%2,%3};\n"
                    : "+f"(acc[nb].x), "+f"(acc[nb].y), "+f"(acc[nb].z), "+f"(acc[nb].w)
                    : "r"(a0), "r"(a1), "r"(a2v), "r"(a3), "r"(b0), "r"(b1));
            }
        }
    }

    // --- Z reduction: rows it (lanes 0-15) and it+8 (lanes 16-31) ---
#pragma unroll
    for (int it = 0; it < 8; ++it) {
        float v = zp[it];
#pragma unroll
        for (int o = 8; o; o >>= 1) v += __shfl_xor_sync(0xffffffffu, v, o);
        if (c == 0) Zs[w * 16 + 8 * h + it] = v;   // lane 0 and lane 16 write
    }
    __syncthreads();

    // --- epilogue: relu(D / Z) ---
    float inv0 = 1.0f / Zs[w * 16 + g];
    float inv1 = 1.0f / Zs[w * 16 + g + 8];
    float* outb = out + ((size_t)b * NN + wrow0) * UU;
#pragma unroll
    for (int nb = 0; nb < 8; ++nb) {
        int col = nb * 8 + tig * 2;
        float2 v0 = make_float2(fmaxf(acc[nb].x * inv0, 0.f), fmaxf(acc[nb].y * inv0, 0.f));
        float2 v1 = make_float2(fmaxf(acc[nb].z * inv1, 0.f), fmaxf(acc[nb].w * inv1, 0.f));
        *(float2*)(outb + (size_t)g * UU + col) = v0;
        *(float2*)(outb + (size_t)(g + 8) * UU + col) = v1;
    }
}

// ---------------------------------------------------------------------------
extern "C" void kernel_launch(void* const* d_in, const int* in_sizes, int n_in,
                              void* d_out, int out_size) {
    const float* H = (const float*)d_in[0];       // [8,4096,128]
    const float* Amask = (const float*)d_in[1];   // [8,4096,4096]
    const float* W = (const float*)d_in[2];       // [128,64]
    const float* a1 = (const float*)d_in[3];      // [64,1]
    const float* a2 = (const float*)d_in[4];      // [64,1]
    float* out = (float*)d_out;                   // [8,4096,64]

    cudaFuncSetAttribute(gat_kernel, cudaFuncAttributeMaxDynamicSharedMemorySize, SMEM_MAIN);

    xgemm_kernel<<<(BATCH * NN) / 64, 256>>>(H, W);
    st_kernel<<<(BATCH * NN) / 8, 256>>>(a1, a2);
    gat_kernel<<<dim3(NN / 128, BATCH), 256, SMEM_MAIN>>>(Amask, out);
}